// round 1
// baseline (speedup 1.0000x reference)
#include <cuda_runtime.h>

// PatchTokenizer: one CTA per 32x32 coarse region (B=16, 16x16 regions => 4096 CTAs).
// Reads its 32x32x3 tile once, builds four 512-bin sub-histograms in smem,
// derives e16 (x4), e32 (hist sum), masks, seqlens (atomic), and writes all
// three masked patch layouts directly from the smem tile.

constexpr int Bsz = 16;

constexpr int OFF_E16 = 0;                                 // 16*32*32      = 16384
constexpr int OFF_E32 = OFF_E16 + 16 * 32 * 32;            // +16384 -> 16384 (len 4096)
constexpr int OFF_M16 = OFF_E32 + 16 * 16 * 16;            // 20480 (len 16384)
constexpr int OFF_M32 = OFF_M16 + 16 * 32 * 32;            // 36864 (len 4096)
constexpr int OFF_SEQ = OFF_M32 + 16 * 16 * 16;            // 40960 (len 16)
constexpr int OFF_P16 = OFF_SEQ + 16;                      // 40976 (len 12582912)
constexpr int OFF_P32 = OFF_P16 + 16 * 32 * 32 * 3 * 256;  // 12623888 (len 3145728)
constexpr int OFF_F32 = OFF_P32 + 16 * 16 * 16 * 3 * 256;  // 15769616 (len 12582912)

__global__ __launch_bounds__(256) void tok_kernel(
    const float* __restrict__ img,
    const float* __restrict__ meanp,
    const float* __restrict__ stdp,
    float* __restrict__ out)
{
    __shared__ float tile[3][32][32];      // 12 KB raw region pixels
    __shared__ unsigned int hist[4][512];  // 8 KB sub-patch histograms
    __shared__ float redbuf[8][5];
    __shared__ float s_m32;

    const int t   = threadIdx.x;
    const int blk = blockIdx.x;
    const int b   = blk >> 8;        // batch
    const int reg = blk & 255;
    const int rh  = reg >> 4;        // coarse patch row (0..15)
    const int rw  = reg & 15;        // coarse patch col

    // zero histograms
    for (int i = t; i < 4 * 512; i += 256)
        ((unsigned int*)hist)[i] = 0;

    // Each thread owns one float4 of the 32x32 tile: row r, cols c4..c4+3
    const int r  = t >> 3;           // 0..31
    const int c4 = (t & 7) << 2;     // 0,4,...,28
    const int grow = rh * 32 + r;
    const int gcol = rw * 32 + c4;

    float gx = 0.f, gy = 0.f, gz = 0.f, gw = 0.f;
    #pragma unroll
    for (int c = 0; c < 3; ++c) {
        const float wgt = (c == 0) ? 0.2989f : ((c == 1) ? 0.587f : 0.114f);
        const float mc = meanp[c];
        const float sc = stdp[c];
        const float4 v = *reinterpret_cast<const float4*>(
            img + (((b * 3 + c) * 512 + grow) * 512 + gcol));
        *reinterpret_cast<float4*>(&tile[c][r][c4]) = v;
        // match reference op order: clip((x*std + mean)*255, 0, 255)
        gx += wgt * fminf(fmaxf((v.x * sc + mc) * 255.0f, 0.0f), 255.0f);
        gy += wgt * fminf(fmaxf((v.y * sc + mc) * 255.0f, 0.0f), 255.0f);
        gz += wgt * fminf(fmaxf((v.z * sc + mc) * 255.0f, 0.0f), 255.0f);
        gw += wgt * fminf(fmaxf((v.w * sc + mc) * 255.0f, 0.0f), 255.0f);
    }
    __syncthreads();  // hist zeroed + tile populated

    // quantize to 512 bins (gray * 512/256 = gray*2), accumulate per 16x16 sub-patch
    const int sub = ((r >> 4) << 1) | (c4 >> 4);  // vertical-major sub index
    atomicAdd(&hist[sub][min(max((int)(gx * 2.0f), 0), 511)], 1u);
    atomicAdd(&hist[sub][min(max((int)(gy * 2.0f), 0), 511)], 1u);
    atomicAdd(&hist[sub][min(max((int)(gz * 2.0f), 0), 511)], 1u);
    atomicAdd(&hist[sub][min(max((int)(gw * 2.0f), 0), 511)], 1u);
    __syncthreads();

    // entropy partials: 4 fine (n/256) + 1 coarse (sum, n/1024)
    float pe0 = 0.f, pe1 = 0.f, pe2 = 0.f, pe3 = 0.f, pe4 = 0.f;
    const float inv16 = 1.0f / 256.0f;
    const float inv32 = 1.0f / 1024.0f;
    for (int bin = t; bin < 512; bin += 256) {
        const float h0 = (float)hist[0][bin];
        const float h1 = (float)hist[1][bin];
        const float h2 = (float)hist[2][bin];
        const float h3 = (float)hist[3][bin];
        float p;
        p = h0 * inv16; pe0 += p * log2f(p + 1e-10f);
        p = h1 * inv16; pe1 += p * log2f(p + 1e-10f);
        p = h2 * inv16; pe2 += p * log2f(p + 1e-10f);
        p = h3 * inv16; pe3 += p * log2f(p + 1e-10f);
        p = (h0 + h1 + h2 + h3) * inv32; pe4 += p * log2f(p + 1e-10f);
    }
    const int lane = t & 31;
    const int wp   = t >> 5;
    #pragma unroll
    for (int o = 16; o; o >>= 1) {
        pe0 += __shfl_down_sync(0xffffffffu, pe0, o);
        pe1 += __shfl_down_sync(0xffffffffu, pe1, o);
        pe2 += __shfl_down_sync(0xffffffffu, pe2, o);
        pe3 += __shfl_down_sync(0xffffffffu, pe3, o);
        pe4 += __shfl_down_sync(0xffffffffu, pe4, o);
    }
    if (lane == 0) {
        redbuf[wp][0] = pe0; redbuf[wp][1] = pe1; redbuf[wp][2] = pe2;
        redbuf[wp][3] = pe3; redbuf[wp][4] = pe4;
    }
    __syncthreads();

    if (t == 0) {
        float s0 = 0.f, s1 = 0.f, s2 = 0.f, s3 = 0.f, s4 = 0.f;
        #pragma unroll
        for (int w = 0; w < 8; ++w) {
            s0 += redbuf[w][0]; s1 += redbuf[w][1]; s2 += redbuf[w][2];
            s3 += redbuf[w][3]; s4 += redbuf[w][4];
        }
        const float e32v = -s4;
        const float m32  = (e32v < 7.0f) ? 1.0f : 0.0f;
        const float m16  = 1.0f - m32;
        const int ridx32 = (b * 16 + rh) * 16 + rw;
        out[OFF_E32 + ridx32] = e32v;
        out[OFF_M32 + ridx32] = m32;
        const float ev[4] = { -s0, -s1, -s2, -s3 };
        #pragma unroll
        for (int s = 0; s < 4; ++s) {
            const int h16 = rh * 2 + (s >> 1);
            const int w16 = rw * 2 + (s & 1);
            const int idx = (b * 32 + h16) * 32 + w16;
            out[OFF_E16 + idx] = ev[s];
            out[OFF_M16 + idx] = m16;
        }
        atomicAdd(&out[OFF_SEQ + b], (m32 > 0.5f) ? 1.0f : 4.0f);
        s_m32 = m32;
    }
    __syncthreads();

    const float m32f = s_m32;
    const float m16f = 1.0f - m32f;

    // ---- p16m (B,32,32,C,16,16) and f32m (B,16,16,4,C,16,16) from raw tile ----
    {
        const int h16 = rh * 2 + (r >> 4);
        const int w16 = rw * 2 + (c4 >> 4);
        const int pr  = r & 15;
        const int pc  = c4 & 15;
        const int n   = ((r >> 4) << 1) | (c4 >> 4);  // n1*2+n2
        #pragma unroll
        for (int c = 0; c < 3; ++c) {
            const float4 v = *reinterpret_cast<const float4*>(&tile[c][r][c4]);
            float4 v16 = make_float4(v.x * m16f, v.y * m16f, v.z * m16f, v.w * m16f);
            float4 v32 = make_float4(v.x * m32f, v.y * m32f, v.z * m32f, v.w * m32f);
            const int d16 = OFF_P16 +
                ((((b * 32 + h16) * 32 + w16) * 3 + c) * 16 + pr) * 16 + pc;
            const int d32 = OFF_F32 +
                (((((b * 16 + rh) * 16 + rw) * 4 + n) * 3 + c) * 16 + pr) * 16 + pc;
            *reinterpret_cast<float4*>(out + d16) = v16;
            *reinterpret_cast<float4*>(out + d32) = v32;
        }
    }

    // ---- p32m (B,16,16,C,16,16): 2x2 average pool of tile, masked ----
    if (t < 192) {
        const int c   = t / 64;            // channel
        const int rem = t & 63;            // 16 rows x 4 float4
        const int pr  = rem >> 2;
        const int pc  = (rem & 3) << 2;    // 0,4,8,12
        const float4 a0 = *reinterpret_cast<const float4*>(&tile[c][2 * pr    ][2 * pc    ]);
        const float4 a1 = *reinterpret_cast<const float4*>(&tile[c][2 * pr    ][2 * pc + 4]);
        const float4 b0 = *reinterpret_cast<const float4*>(&tile[c][2 * pr + 1][2 * pc    ]);
        const float4 b1 = *reinterpret_cast<const float4*>(&tile[c][2 * pr + 1][2 * pc + 4]);
        float4 o;
        o.x = (a0.x + a0.y + b0.x + b0.y) * 0.25f * m32f;
        o.y = (a0.z + a0.w + b0.z + b0.w) * 0.25f * m32f;
        o.z = (a1.x + a1.y + b1.x + b1.y) * 0.25f * m32f;
        o.w = (a1.z + a1.w + b1.z + b1.w) * 0.25f * m32f;
        const int d = OFF_P32 +
            ((((b * 16 + rh) * 16 + rw) * 3 + c) * 16 + pr) * 16 + pc;
        *reinterpret_cast<float4*>(out + d) = o;
    }
}

extern "C" void kernel_launch(void* const* d_in, const int* in_sizes, int n_in,
                              void* d_out, int out_size)
{
    const float* img   = (const float*)d_in[0];
    const float* meanp = (const float*)d_in[1];
    const float* stdp  = (const float*)d_in[2];
    float* out = (float*)d_out;

    // seqlens accumulated via atomics -> zero it first (graph-capturable memset node)
    cudaMemsetAsync(out + OFF_SEQ, 0, Bsz * sizeof(float));

    tok_kernel<<<16 * 16 * 16, 256>>>(img, meanp, stdp, out);
}

// round 2
// speedup vs baseline: 1.1778x; 1.1778x over previous
#include <cuda_runtime.h>

// PatchTokenizer: one CTA per 32x32 coarse region (B=16, 16x16 regions => 4096 CTAs).
// R2: no smem tile. Pixels live in registers across the histogram/entropy phase;
// 2x2 pooling for p32m done via warp shuffle (t^8 = vertical neighbor row).
// Smem = 4x512 hist (8KB) + reduction scratch only.

constexpr int Bsz = 16;

constexpr int OFF_E16 = 0;                                 // len 16384
constexpr int OFF_E32 = OFF_E16 + 16 * 32 * 32;            // len 4096
constexpr int OFF_M16 = OFF_E32 + 16 * 16 * 16;            // len 16384
constexpr int OFF_M32 = OFF_M16 + 16 * 32 * 32;            // len 4096
constexpr int OFF_SEQ = OFF_M32 + 16 * 16 * 16;            // len 16
constexpr int OFF_P16 = OFF_SEQ + 16;                      // len 12582912
constexpr int OFF_P32 = OFF_P16 + 16 * 32 * 32 * 3 * 256;  // len 3145728
constexpr int OFF_F32 = OFF_P32 + 16 * 16 * 16 * 3 * 256;  // len 12582912

__global__ __launch_bounds__(256, 5) void tok_kernel(
    const float* __restrict__ img,
    const float* __restrict__ meanp,
    const float* __restrict__ stdp,
    float* __restrict__ out)
{
    __shared__ unsigned int hist[4][512];  // 8 KB sub-patch histograms
    __shared__ float redbuf[8][5];
    __shared__ float s_m32;

    const int t   = threadIdx.x;
    const int blk = blockIdx.x;
    const int b   = blk >> 8;        // batch
    const int reg = blk & 255;
    const int rh  = reg >> 4;        // coarse patch row (0..15)
    const int rw  = reg & 15;        // coarse patch col

    // zero histograms (vectorized: 512 uint4 total)
    {
        const uint4 z = make_uint4(0u, 0u, 0u, 0u);
        reinterpret_cast<uint4*>(hist)[t]       = z;
        reinterpret_cast<uint4*>(hist)[t + 256] = z;
    }

    // Each thread owns one float4 of the 32x32 tile: row r, cols c4..c4+3
    const int r  = t >> 3;           // 0..31
    const int c4 = (t & 7) << 2;     // 0,4,...,28
    const int grow = rh * 32 + r;
    const int gcol = rw * 32 + c4;

    float4 v[3];
    float gx = 0.f, gy = 0.f, gz = 0.f, gw = 0.f;
    #pragma unroll
    for (int c = 0; c < 3; ++c) {
        const float wgt = (c == 0) ? 0.2989f : ((c == 1) ? 0.587f : 0.114f);
        const float mc = meanp[c];
        const float sc = stdp[c];
        const float4 px = *reinterpret_cast<const float4*>(
            img + (((b * 3 + c) * 512 + grow) * 512 + gcol));
        v[c] = px;
        // match reference op order: clip((x*std + mean)*255, 0, 255)
        gx += wgt * fminf(fmaxf((px.x * sc + mc) * 255.0f, 0.0f), 255.0f);
        gy += wgt * fminf(fmaxf((px.y * sc + mc) * 255.0f, 0.0f), 255.0f);
        gz += wgt * fminf(fmaxf((px.z * sc + mc) * 255.0f, 0.0f), 255.0f);
        gw += wgt * fminf(fmaxf((px.w * sc + mc) * 255.0f, 0.0f), 255.0f);
    }
    __syncthreads();  // hist zeroed

    // quantize to 512 bins (gray * 2), accumulate per 16x16 sub-patch
    const int sub = ((r >> 4) << 1) | (c4 >> 4);
    atomicAdd(&hist[sub][min(max((int)(gx * 2.0f), 0), 511)], 1u);
    atomicAdd(&hist[sub][min(max((int)(gy * 2.0f), 0), 511)], 1u);
    atomicAdd(&hist[sub][min(max((int)(gz * 2.0f), 0), 511)], 1u);
    atomicAdd(&hist[sub][min(max((int)(gw * 2.0f), 0), 511)], 1u);
    __syncthreads();

    // entropy partials: each thread handles bins 2t and 2t+1 (512 bins / 256 thr)
    float pe0, pe1, pe2, pe3, pe4;
    {
        const uint2 h0 = *reinterpret_cast<const uint2*>(&hist[0][2 * t]);
        const uint2 h1 = *reinterpret_cast<const uint2*>(&hist[1][2 * t]);
        const uint2 h2 = *reinterpret_cast<const uint2*>(&hist[2][2 * t]);
        const uint2 h3 = *reinterpret_cast<const uint2*>(&hist[3][2 * t]);
        const float inv16 = 1.0f / 256.0f;
        const float inv32 = 1.0f / 1024.0f;
        float p;
        p = (float)h0.x * inv16; pe0  = p * __log2f(p + 1e-10f);
        p = (float)h0.y * inv16; pe0 += p * __log2f(p + 1e-10f);
        p = (float)h1.x * inv16; pe1  = p * __log2f(p + 1e-10f);
        p = (float)h1.y * inv16; pe1 += p * __log2f(p + 1e-10f);
        p = (float)h2.x * inv16; pe2  = p * __log2f(p + 1e-10f);
        p = (float)h2.y * inv16; pe2 += p * __log2f(p + 1e-10f);
        p = (float)h3.x * inv16; pe3  = p * __log2f(p + 1e-10f);
        p = (float)h3.y * inv16; pe3 += p * __log2f(p + 1e-10f);
        p = (float)(h0.x + h1.x + h2.x + h3.x) * inv32; pe4  = p * __log2f(p + 1e-10f);
        p = (float)(h0.y + h1.y + h2.y + h3.y) * inv32; pe4 += p * __log2f(p + 1e-10f);
    }
    const int lane = t & 31;
    const int wp   = t >> 5;
    #pragma unroll
    for (int o = 16; o; o >>= 1) {
        pe0 += __shfl_down_sync(0xffffffffu, pe0, o);
        pe1 += __shfl_down_sync(0xffffffffu, pe1, o);
        pe2 += __shfl_down_sync(0xffffffffu, pe2, o);
        pe3 += __shfl_down_sync(0xffffffffu, pe3, o);
        pe4 += __shfl_down_sync(0xffffffffu, pe4, o);
    }
    if (lane == 0) {
        redbuf[wp][0] = pe0; redbuf[wp][1] = pe1; redbuf[wp][2] = pe2;
        redbuf[wp][3] = pe3; redbuf[wp][4] = pe4;
    }
    __syncthreads();

    if (t == 0) {
        float s0 = 0.f, s1 = 0.f, s2 = 0.f, s3 = 0.f, s4 = 0.f;
        #pragma unroll
        for (int w = 0; w < 8; ++w) {
            s0 += redbuf[w][0]; s1 += redbuf[w][1]; s2 += redbuf[w][2];
            s3 += redbuf[w][3]; s4 += redbuf[w][4];
        }
        const float e32v = -s4;
        const float m32  = (e32v < 7.0f) ? 1.0f : 0.0f;
        const float m16  = 1.0f - m32;
        const int ridx32 = (b * 16 + rh) * 16 + rw;
        out[OFF_E32 + ridx32] = e32v;
        out[OFF_M32 + ridx32] = m32;
        const float ev[4] = { -s0, -s1, -s2, -s3 };
        #pragma unroll
        for (int s = 0; s < 4; ++s) {
            const int h16 = rh * 2 + (s >> 1);
            const int w16 = rw * 2 + (s & 1);
            const int idx = (b * 32 + h16) * 32 + w16;
            out[OFF_E16 + idx] = ev[s];
            out[OFF_M16 + idx] = m16;
        }
        atomicAdd(&out[OFF_SEQ + b], (m32 > 0.5f) ? 1.0f : 4.0f);
        s_m32 = m32;
    }
    __syncthreads();

    const float m32f = s_m32;
    const float m16f = 1.0f - m32f;

    // ---- stores straight from registers ----
    const int region = (b * 16 + rh) * 16 + rw;
    const int h16 = rh * 2 + (r >> 4);
    const int w16 = rw * 2 + (c4 >> 4);
    const int pr  = r & 15;
    const int pc  = c4 & 15;
    const int n   = ((r >> 4) << 1) | (c4 >> 4);  // n1*2+n2

    float* __restrict__ p16b = out + OFF_P16 + (size_t)(((b * 32 + h16) * 32 + w16)) * 768;
    float* __restrict__ f32b = out + OFF_F32 + (size_t)(region * 4 + n) * 768;
    float* __restrict__ p32b = out + OFF_P32 + (size_t)region * 768;
    const int inner   = pr * 16 + pc;
    const int inner32 = (r >> 1) * 16 + (c4 >> 1);
    const bool evenRow = (r & 1) == 0;
    const float qm = 0.25f * m32f;

    #pragma unroll
    for (int c = 0; c < 3; ++c) {
        const float4 px = v[c];
        const float4 v16 = make_float4(px.x * m16f, px.y * m16f, px.z * m16f, px.w * m16f);
        const float4 v32 = make_float4(px.x * m32f, px.y * m32f, px.z * m32f, px.w * m32f);
        *reinterpret_cast<float4*>(p16b + c * 256 + inner) = v16;
        *reinterpret_cast<float4*>(f32b + c * 256 + inner) = v32;

        // 2x2 pool via shuffle: partner thread t^8 owns row r^1, same columns
        const float hx = px.x + px.y;
        const float hy = px.z + px.w;
        const float ox = hx + __shfl_xor_sync(0xffffffffu, hx, 8);
        const float oy = hy + __shfl_xor_sync(0xffffffffu, hy, 8);
        if (evenRow) {
            *reinterpret_cast<float2*>(p32b + c * 256 + inner32) =
                make_float2(ox * qm, oy * qm);
        }
    }
}

extern "C" void kernel_launch(void* const* d_in, const int* in_sizes, int n_in,
                              void* d_out, int out_size)
{
    const float* img   = (const float*)d_in[0];
    const float* meanp = (const float*)d_in[1];
    const float* stdp  = (const float*)d_in[2];
    float* out = (float*)d_out;

    // seqlens accumulated via atomics -> zero it first (graph-capturable memset node)
    cudaMemsetAsync(out + OFF_SEQ, 0, Bsz * sizeof(float));

    tok_kernel<<<16 * 16 * 16, 256>>>(img, meanp, stdp, out);
}